// round 6
// baseline (speedup 1.0000x reference)
#include <cuda_runtime.h>
#include <cstdint>

// ---------------------------------------------------------------------------
// minLSTM cell, fused: grouped linears + gate math + scan.
// f32x2 FMA along the K (dot-product) axis: operand pairs come directly from
// float4 load registers and loop-invariant packed weights -> no per-element
// packing ALU cost (the R5 mistake).
//
// Shapes: x (B=4, S=8192, D=1024), W* (128 groups, 8, 8), out (4, 8192, 1024).
//
// Exact algebraic rewrite of the reference:
//   F,I,G = grouped 8x8 linears
//   eF=exp(-F), eI=exp(-I), s = 2+eF+eI
//   f = (1+eI)/s * exp(EPS)   (EPS folded from cumsum(log_f + EPS))
//   i = (1+eF)/s
//   g = G>=0 ? G+0.5+1e-8 : sigmoid(G)
//   h_t = f_t * h_{t-1} + i_t * g_t,  h_{-1} = 0
//
// Wf, Wi pre-scaled by -log2(e) so eF = ex2(dotF) directly.
// One CTA per (batch, group-quad) chain of 32 channels; 16 warps = 16 time
// slabs of 16 t each per 256-t iteration; smem double-buffered carry.
// ---------------------------------------------------------------------------

namespace {
constexpr int kS       = 8192;
constexpr int kD       = 1024;
constexpr int kWarps   = 16;
constexpr int kThreads = kWarps * 32;            // 512
constexpr int kTper    = 16;                     // timesteps per thread
constexpr int kIterT   = kWarps * kTper;         // 256 timesteps per iteration
constexpr int kNIter   = kS / kIterT;            // 32
constexpr int kNChain  = 128;                    // 4 batches * 32 group-quads
constexpr float kNegLog2e = -1.4426950408889634f;
}  // namespace

__device__ float g_wf2[128 * 64];                // Wf * -log2(e)
__device__ float g_wi2[128 * 64];                // Wi * -log2(e)

__global__ void prep_kernel(const float* __restrict__ Wf,
                            const float* __restrict__ Wi) {
  int i = blockIdx.x * blockDim.x + threadIdx.x;
  if (i < 128 * 64) {
    g_wf2[i] = Wf[i] * kNegLog2e;
    g_wi2[i] = Wi[i] * kNegLog2e;
  }
}

using ull = unsigned long long;

union F4U {
  float4 v;
  ull    u[2];
};

__device__ __forceinline__ ull pack2(float lo, float hi) {
  ull r;
  asm("mov.b64 %0, {%1, %2};" : "=l"(r) : "f"(lo), "f"(hi));
  return r;
}
__device__ __forceinline__ void unpack2(ull p, float& lo, float& hi) {
  asm("mov.b64 {%0, %1}, %2;" : "=f"(lo), "=f"(hi) : "l"(p));
}
__device__ __forceinline__ ull fma2(ull a, ull b, ull c) {
  ull d;
  asm("fma.rn.f32x2 %0, %1, %2, %3;" : "=l"(d) : "l"(a), "l"(b), "l"(c));
  return d;
}
__device__ __forceinline__ ull mul2(ull a, ull b) {
  ull d;
  asm("mul.rn.f32x2 %0, %1, %2;" : "=l"(d) : "l"(a), "l"(b));
  return d;
}
__device__ __forceinline__ float hadd2(ull p) {
  float lo, hi;
  unpack2(p, lo, hi);
  return lo + hi;
}
__device__ __forceinline__ float ex2f(float x) {
  float r;
  asm("ex2.approx.f32 %0, %1;" : "=f"(r) : "f"(x));
  return r;
}
__device__ __forceinline__ float frcp(float x) {
  float r;
  asm("rcp.approx.f32 %0, %1;" : "=f"(r) : "f"(x));
  return r;
}

// Fd, Id are pre-scaled dots (-F*log2e, -I*log2e); G is the raw hidden dot.
__device__ __forceinline__ void gate_tail(float Fd, float Id, float G,
                                          float& f, float& v) {
  const float eF = ex2f(Fd);                     // e^{-F}
  const float eI = ex2f(Id);                     // e^{-I}
  const float eG = ex2f(G * kNegLog2e);          // e^{-G}
  const float s  = 2.f + eF + eI;
  const float rd = frcp(s);
  const float f0 = fmaf(eI, rd, rd);             // (1+eI)/s
  f = fmaf(f0, 1e-8f, f0);                       // * exp(EPS) from cumsum(+EPS)
  const float ic = fmaf(eF, rd, rd);             // (1+eF)/s
  const float g  = (G >= 0.f) ? (G + 0.5f + 1e-8f) : frcp(1.f + eG);
  v = ic * g;
}

__global__ __launch_bounds__(kThreads, 1) void minlstm_kernel(
    const float* __restrict__ x, const float* __restrict__ Wh,
    float* __restrict__ out) {
  const int chain = blockIdx.x;                  // 0..127
  const int b     = chain >> 5;
  const int gq    = chain & 31;                  // group-quad (4 groups, 32 ch)
  const int w     = threadIdx.x >> 5;            // warp = time slab
  const int c     = threadIdx.x & 31;            // lane = channel

  // Loop-invariant packed weight pairs (K-axis pairs): packed ONCE.
  const int row = gq * 32 + c;
  F4U wfA, wfB, wiA, wiB, whA, whB;
  wfA.v = *reinterpret_cast<const float4*>(g_wf2 + row * 8);
  wfB.v = *reinterpret_cast<const float4*>(g_wf2 + row * 8 + 4);
  wiA.v = *reinterpret_cast<const float4*>(g_wi2 + row * 8);
  wiB.v = *reinterpret_cast<const float4*>(g_wi2 + row * 8 + 4);
  whA.v = *reinterpret_cast<const float4*>(Wh + row * 8);
  whB.v = *reinterpret_cast<const float4*>(Wh + row * 8 + 4);

  __shared__ float2 sc[kWarps][32];
  __shared__ float  Hs[2][32];
  if (threadIdx.x < 32) { Hs[0][c] = 0.f; Hs[1][c] = 0.f; }

  const float* xbase = x + (size_t)b * kS * kD + gq * 32 + (c & 24);
  float* obase       = out + (size_t)b * kS * kD + gq * 32 + c;

  for (int iter = 0; iter < kNIter; iter++) {
    const int t0 = iter * kIterT + w * kTper;
    const float* xp = xbase + (size_t)t0 * kD;

    float aj[kTper], bj[kTper];
    float A = 1.f, Bv = 0.f;                     // running affine for this slab
#pragma unroll
    for (int j = 0; j < kTper; j++) {
      F4U xa, xb;
      xa.v = *reinterpret_cast<const float4*>(xp + (size_t)j * kD);
      xb.v = *reinterpret_cast<const float4*>(xp + (size_t)j * kD + 4);

      // 8-dots as 4x f32x2 FMA; operand pairs are native register pairs.
      ull F2 = mul2(xa.u[0], wfA.u[0]);
      F2 = fma2(xa.u[1], wfA.u[1], F2);
      F2 = fma2(xb.u[0], wfB.u[0], F2);
      F2 = fma2(xb.u[1], wfB.u[1], F2);

      ull I2 = mul2(xa.u[0], wiA.u[0]);
      I2 = fma2(xa.u[1], wiA.u[1], I2);
      I2 = fma2(xb.u[0], wiB.u[0], I2);
      I2 = fma2(xb.u[1], wiB.u[1], I2);

      ull G2 = mul2(xa.u[0], whA.u[0]);
      G2 = fma2(xa.u[1], whA.u[1], G2);
      G2 = fma2(xb.u[0], whB.u[0], G2);
      G2 = fma2(xb.u[1], whB.u[1], G2);

      const float Fd = hadd2(F2);
      const float Id = hadd2(I2);
      const float G  = hadd2(G2);

      float f, v;
      gate_tail(Fd, Id, G, f, v);
      aj[j] = f;
      bj[j] = v;
      A *= f;
      Bv = fmaf(f, Bv, v);
    }

    sc[w][c] = make_float2(A, Bv);
    __syncthreads();                             // sc visible; Hs[buf] stable

    // Exclusive prefix over earlier slabs for this channel.
    float Ae = 1.f, Be = 0.f;
    for (int k = 0; k < w; k++) {
      const float2 p = sc[k][c];
      Be = fmaf(p.x, Be, p.y);
      Ae *= p.x;
    }

    const float Hp = Hs[iter & 1][c];            // carry entering this iteration

    // Last slab publishes next carry into the other buffer (readers sync at
    // the next iteration's __syncthreads()).
    if (w == kWarps - 1) {
      Hs[(iter + 1) & 1][c] = fmaf(A * Ae, Hp, fmaf(A, Be, Bv));
    }

    // Apply carry and emit; lanes are 32 contiguous floats -> coalesced 128B.
    float h = fmaf(Ae, Hp, Be);
    float* op = obase + (size_t)t0 * kD;
#pragma unroll
    for (int j = 0; j < kTper; j++) {
      h = fmaf(aj[j], h, bj[j]);
      op[(size_t)j * kD] = h;
    }
  }
}

extern "C" void kernel_launch(void* const* d_in, const int* in_sizes, int n_in,
                              void* d_out, int out_size) {
  (void)in_sizes; (void)n_in; (void)out_size;
  const float* x  = (const float*)d_in[0];
  const float* Wf = (const float*)d_in[1];
  const float* Wi = (const float*)d_in[2];
  const float* Wh = (const float*)d_in[3];
  float* out = (float*)d_out;

  prep_kernel<<<32, 256>>>(Wf, Wi);
  minlstm_kernel<<<kNChain, kThreads>>>(x, Wh, out);
}

// round 9
// speedup vs baseline: 1.3138x; 1.3138x over previous
#include <cuda_runtime.h>
#include <cstdint>

// ---------------------------------------------------------------------------
// minLSTM cell, fused: grouped linears + gate math + scan.
// cp.async double-buffered smem staging of x (kills LDG latency exposure),
// scalar FFMA dots, Wf/Wi pre-scaled by -log2(e).
//
// Shapes: x (B=4, S=8192, D=1024), W* (128 groups, 8, 8), out (4, 8192, 1024).
//
// Exact algebraic rewrite of the reference:
//   F,I,G = grouped 8x8 linears
//   eF=exp(-F), eI=exp(-I), s = 2+eF+eI
//   f = (1+eI)/s      (exp(EPS) cumsum factor dropped: bias <= 8.2e-5)
//   i = (1+eF)/s
//   g = G>=0 ? G+0.5+1e-8 : sigmoid(G)
//   h_t = f_t * h_{t-1} + i_t * g_t,  h_{-1} = 0
//
// One CTA per (batch, group-quad) chain of 32 channels; 16 warps = 16 time
// slabs of 8 t each per 128-t iteration; smem double-buffered carry.
// No inter-block communication anywhere.
// ---------------------------------------------------------------------------

namespace {
constexpr int kS       = 8192;
constexpr int kD       = 1024;
constexpr int kWarps   = 16;
constexpr int kThreads = kWarps * 32;            // 512
constexpr int kTper    = 8;                      // timesteps per thread
constexpr int kIterT   = kWarps * kTper;         // 128 timesteps per iteration
constexpr int kNIter   = kS / kIterT;            // 64
constexpr int kNChain  = 128;                    // 4 batches * 32 group-quads
constexpr float kNegLog2e = -1.4426950408889634f;
}  // namespace

__device__ float g_wf2[128 * 64];                // Wf * -log2(e)
__device__ float g_wi2[128 * 64];                // Wi * -log2(e)

__global__ void prep_kernel(const float* __restrict__ Wf,
                            const float* __restrict__ Wi) {
  int i = blockIdx.x * blockDim.x + threadIdx.x;
  if (i < 128 * 64) {
    g_wf2[i] = Wf[i] * kNegLog2e;
    g_wi2[i] = Wi[i] * kNegLog2e;
  }
}

__device__ __forceinline__ float ex2f(float x) {
  float r;
  asm("ex2.approx.f32 %0, %1;" : "=f"(r) : "f"(x));
  return r;
}
__device__ __forceinline__ float frcp(float x) {
  float r;
  asm("rcp.approx.f32 %0, %1;" : "=f"(r) : "f"(x));
  return r;
}
__device__ __forceinline__ void cp_async16(uint32_t saddr, const void* gaddr) {
  asm volatile("cp.async.cg.shared.global [%0], [%1], 16;"
               :: "r"(saddr), "l"(gaddr));
}
__device__ __forceinline__ uint32_t smem_u32(const void* p) {
  uint32_t a;
  asm("{ .reg .u64 t; cvta.to.shared.u64 t, %1; cvt.u32.u64 %0, t; }"
      : "=r"(a) : "l"(p));
  return a;
}

__global__ __launch_bounds__(kThreads, 1) void minlstm_kernel(
    const float* __restrict__ x, const float* __restrict__ Wh,
    float* __restrict__ out) {
  const int chain = blockIdx.x;                  // 0..127
  const int b     = chain >> 5;
  const int gq    = chain & 31;                  // group-quad (4 groups, 32 ch)
  const int w     = threadIdx.x >> 5;            // warp = time slab
  const int c     = threadIdx.x & 31;            // lane = channel

  // Per-channel weight rows; 8 lanes of a group share x inputs.
  const int row = gq * 32 + c;
  const float4 wf0 = *reinterpret_cast<const float4*>(g_wf2 + row * 8);
  const float4 wf1 = *reinterpret_cast<const float4*>(g_wf2 + row * 8 + 4);
  const float4 wi0 = *reinterpret_cast<const float4*>(g_wi2 + row * 8);
  const float4 wi1 = *reinterpret_cast<const float4*>(g_wi2 + row * 8 + 4);
  const float4 wh0 = *reinterpret_cast<const float4*>(Wh + row * 8);
  const float4 wh1 = *reinterpret_cast<const float4*>(Wh + row * 8 + 4);

  __shared__ float  xs[2][kIterT][32];           // 2 x 16KB staging
  __shared__ float2 sc[kWarps][32];
  __shared__ float  Hs[2][32];
  if (threadIdx.x < 32) { Hs[0][c] = 0.f; Hs[1][c] = 0.f; }

  const float* xg = x + (size_t)b * kS * kD + gq * 32;   // chain's x base
  float* obase    = out + (size_t)b * kS * kD + gq * 32 + c;
  const uint32_t xs_base = smem_u32(&xs[0][0][0]);

  // Each thread copies 2 x 16B chunks per slab (128 rows x 8 chunks = 1024).
  const int tl0 = threadIdx.x >> 3;
  const int sg0 = (threadIdx.x & 7) * 4;
  const int tl1 = tl0 + 64;                      // (tid + 512) >> 3
  const int sg1 = sg0;

  // Prefetch slab 0 into buffer 0.
  {
    const float* g0 = xg + (size_t)tl0 * kD + sg0;
    const float* g1 = xg + (size_t)tl1 * kD + sg1;
    cp_async16(xs_base + (tl0 * 32 + sg0) * 4, g0);
    cp_async16(xs_base + (tl1 * 32 + sg1) * 4, g1);
    asm volatile("cp.async.commit_group;");
  }

  for (int iter = 0; iter < kNIter; iter++) {
    const int buf = iter & 1;
    if (iter + 1 < kNIter) {
      // Prefetch next slab into the other buffer (released at the previous
      // iteration's second barrier, which every thread has passed).
      const int nbuf = buf ^ 1;
      const float* g0 = xg + (size_t)((iter + 1) * kIterT + tl0) * kD + sg0;
      const float* g1 = xg + (size_t)((iter + 1) * kIterT + tl1) * kD + sg1;
      cp_async16(xs_base + ((nbuf * kIterT + tl0) * 32 + sg0) * 4, g0);
      cp_async16(xs_base + ((nbuf * kIterT + tl1) * 32 + sg1) * 4, g1);
      asm volatile("cp.async.commit_group;");
      asm volatile("cp.async.wait_group 1;");    // current slab complete
    } else {
      asm volatile("cp.async.wait_group 0;");
    }
    __syncthreads();                             // slab visible; Hs stable

    const float* xp = &xs[buf][w * kTper][c & 24];

    float aj[kTper], bj[kTper];
    float A = 1.f, Bv = 0.f;                     // running affine for this slab
#pragma unroll
    for (int j = 0; j < kTper; j++) {
      const float4 xa = *reinterpret_cast<const float4*>(xp + j * 32);
      const float4 xb = *reinterpret_cast<const float4*>(xp + j * 32 + 4);

      float Fd = xa.x * wf0.x;                   // already scaled by -log2e
      Fd = fmaf(xa.y, wf0.y, Fd); Fd = fmaf(xa.z, wf0.z, Fd); Fd = fmaf(xa.w, wf0.w, Fd);
      Fd = fmaf(xb.x, wf1.x, Fd); Fd = fmaf(xb.y, wf1.y, Fd);
      Fd = fmaf(xb.z, wf1.z, Fd); Fd = fmaf(xb.w, wf1.w, Fd);

      float Id = xa.x * wi0.x;
      Id = fmaf(xa.y, wi0.y, Id); Id = fmaf(xa.z, wi0.z, Id); Id = fmaf(xa.w, wi0.w, Id);
      Id = fmaf(xb.x, wi1.x, Id); Id = fmaf(xb.y, wi1.y, Id);
      Id = fmaf(xb.z, wi1.z, Id); Id = fmaf(xb.w, wi1.w, Id);

      float G = xa.x * wh0.x;
      G = fmaf(xa.y, wh0.y, G); G = fmaf(xa.z, wh0.z, G); G = fmaf(xa.w, wh0.w, G);
      G = fmaf(xb.x, wh1.x, G); G = fmaf(xb.y, wh1.y, G);
      G = fmaf(xb.z, wh1.z, G); G = fmaf(xb.w, wh1.w, G);

      const float eF = ex2f(Fd);                 // e^{-F}
      const float eI = ex2f(Id);                 // e^{-I}
      const float s  = 2.f + eF + eI;
      const float rd = frcp(s);
      const float f  = fmaf(eI, rd, rd);         // (1+eI)/s
      const float ic = fmaf(eF, rd, rd);         // (1+eF)/s
      const float g  = (G >= 0.f) ? (G + 0.5f + 1e-8f)
                                  : frcp(1.f + ex2f(G * kNegLog2e));
      const float v  = ic * g;

      aj[j] = f;
      bj[j] = v;
      A *= f;
      Bv = fmaf(f, Bv, v);
    }

    sc[w][c] = make_float2(A, Bv);
    __syncthreads();                             // sc visible; buffer released

    // Exclusive prefix over earlier slabs for this channel.
    float Ae = 1.f, Be = 0.f;
    for (int k = 0; k < w; k++) {
      const float2 p = sc[k][c];
      Be = fmaf(p.x, Be, p.y);
      Ae *= p.x;
    }

    const float Hp = Hs[iter & 1][c];            // carry entering this iteration

    // Last slab publishes next carry into the other buffer (readers sync at
    // the next iteration's first __syncthreads()).
    if (w == kWarps - 1) {
      Hs[(iter + 1) & 1][c] = fmaf(A * Ae, Hp, fmaf(A, Be, Bv));
    }

    // Apply carry and emit; lanes are 32 contiguous floats -> coalesced 128B.
    float h = fmaf(Ae, Hp, Be);
    float* op = obase + (size_t)(iter * kIterT + w * kTper) * kD;
#pragma unroll
    for (int j = 0; j < kTper; j++) {
      h = fmaf(aj[j], h, bj[j]);
      op[(size_t)j * kD] = h;
    }
  }
}

extern "C" void kernel_launch(void* const* d_in, const int* in_sizes, int n_in,
                              void* d_out, int out_size) {
  (void)in_sizes; (void)n_in; (void)out_size;
  const float* x  = (const float*)d_in[0];
  const float* Wf = (const float*)d_in[1];
  const float* Wi = (const float*)d_in[2];
  const float* Wh = (const float*)d_in[3];
  float* out = (float*)d_out;

  prep_kernel<<<32, 256>>>(Wf, Wi);
  minlstm_kernel<<<kNChain, kThreads>>>(x, Wh, out);
}